// round 9
// baseline (speedup 1.0000x reference)
#include <cuda_runtime.h>
#include <cstdint>

// ---------------------------------------------------------------------------
// FishEyePatchEmbedding on GB300 (sm_103a) — legacy mma.sync tf32 path
// (toolchain lowers via compute_103: tcgen05 PTX unavailable)
//   1) gather+lerp -> A [35328, 768] tf32-truncated, 4 elems/thread (R5 best)
//   2) GEMM 128x64 tiles, warp tile 32x32, 2-stage cp.async, 3 CTAs/SM
// ---------------------------------------------------------------------------

#define PLANE   (736 * 736)
#define NBATCH  32
#define EMB     768
#define KDIM    768
#define OHN     23
#define OWN     48
#define SPP     (OHN * OWN)       // 1104
#define MTOT    (NBATCH * SPP)    // 35328

#define TILE_M  128
#define TILE_N  64
#define KCHUNK  32
#define KB      (KDIM / KCHUNK)   // 24
#define STAGES  2
#define LDSS    36                // padded smem stride (floats)

#define SA_FLOATS  (TILE_M * LDSS)            // 4608
#define SB_FLOATS  (TILE_N * LDSS)            // 2304
#define STG_FLOATS (SA_FLOATS + SB_FLOATS)    // 6912
#define SMEM_BIAS_FLOATS 64
#define SMEM_TOTAL_BYTES ((SMEM_BIAS_FLOATS + STAGES * STG_FLOATS) * 4)  // 55552

__device__ float g_A[(size_t)MTOT * KDIM];    // 108.5 MB scratch
__device__ float g_W[(size_t)EMB * KDIM];     // 2.25 MB tf32 weights

#define GATHER4  (MTOT * (KDIM / 4))          // 6782976
#define WPREP4   (EMB * KDIM / 4)             // 147456

// ---------------------------------------------------------------------------
__device__ __forceinline__ float f2tf32(float f) {
    uint32_t u;
    asm("cvt.rna.tf32.f32 %0, %1;" : "=r"(u) : "f"(f));
    return __uint_as_float(u);
}

// ---------------------------------------------------------------------------
// Gather kernel (R5 best config: 4 k-elems/thread + fused weight prep)
// ---------------------------------------------------------------------------
__global__ void fisheye_gather_kernel(const float* __restrict__ x,
                                      const int*   __restrict__ idx0,
                                      const int*   __restrict__ idx1,
                                      const float* __restrict__ w,
                                      const float* __restrict__ conv_w,
                                      float*       __restrict__ A,
                                      float*       __restrict__ Wt) {
    int e4 = blockIdx.x * blockDim.x + threadIdx.x;
    if (e4 >= GATHER4) {
        int i = e4 - GATHER4;
        if (i < WPREP4) {
            float4 v = reinterpret_cast<const float4*>(conv_w)[i];
            v.x = f2tf32(v.x); v.y = f2tf32(v.y);
            v.z = f2tf32(v.z); v.w = f2tf32(v.w);
            reinterpret_cast<float4*>(Wt)[i] = v;
        }
        return;
    }

    int base = e4 * 4;
    int m = base / KDIM;
    int k = base - m * KDIM;

    int n  = m / SPP;
    int s  = m - n * SPP;
    int oh = s / OWN;
    int ow = s - oh * OWN;

    int c  = k >> 8;
    int r  = k & 255;
    int ky = r >> 4;
    int kx = r & 15;

    int t = (oh * 16 + ky) * 768 + ow * 16 + kx;

    const float* xp = x + (size_t)(n * 3 + c) * PLANE;

    int4   g0 = *reinterpret_cast<const int4*>(idx0 + t);
    int4   g1 = *reinterpret_cast<const int4*>(idx1 + t);
    float4 wt = *reinterpret_cast<const float4*>(w + t);

    float a0 = xp[g0.x], a1 = xp[g0.y], a2 = xp[g0.z], a3 = xp[g0.w];
    float b0 = xp[g1.x], b1 = xp[g1.y], b2 = xp[g1.z], b3 = xp[g1.w];

    float4 o;
    o.x = f2tf32(fmaf(b0 - a0, wt.x, a0));
    o.y = f2tf32(fmaf(b1 - a1, wt.y, a1));
    o.z = f2tf32(fmaf(b2 - a2, wt.z, a2));
    o.w = f2tf32(fmaf(b3 - a3, wt.w, a3));

    *reinterpret_cast<float4*>(A + base) = o;
}

// ---------------------------------------------------------------------------
__device__ __forceinline__ void cp16s(uint32_t sdst, const void* gsrc) {
    asm volatile("cp.async.cg.shared.global [%0], [%1], 16;" :: "r"(sdst), "l"(gsrc));
}
__device__ __forceinline__ void ldsm4(uint32_t& r0, uint32_t& r1,
                                      uint32_t& r2, uint32_t& r3, uint32_t a) {
    asm volatile("ldmatrix.sync.aligned.m8n8.x4.shared.b16 {%0,%1,%2,%3}, [%4];"
                 : "=r"(r0), "=r"(r1), "=r"(r2), "=r"(r3) : "r"(a));
}

// ---------------------------------------------------------------------------
// GEMM: grid (12, 276), 256 threads (8 warps 4x2), warp tile 32x32,
// 2-stage cp.async double buffer, 3 CTAs/SM (reg-capped at ~80).
// ---------------------------------------------------------------------------
__global__ void __launch_bounds__(256, 3)
fisheye_gemm_kernel(const float* __restrict__ A,
                    const float* __restrict__ Wm,
                    const float* __restrict__ bias,
                    float*       __restrict__ out) {
    extern __shared__ float smem[];
    float* biass  = smem;
    float* stage0 = smem + SMEM_BIAS_FLOATS;

    const int tid  = threadIdx.x;
    const int lane = tid & 31;
    const int warp = tid >> 5;
    const int wm   = (warp >> 1) * 32;   // 0,32,64,96
    const int wn   = (warp & 1) * 32;    // 0,32
    const int gId  = lane >> 2;
    const int tig  = lane & 3;

    const int nTile = blockIdx.x;
    const int mTile = blockIdx.y;

    const float* Ag = A  + (size_t)mTile * TILE_M * KDIM;
    const float* Bg = Wm + (size_t)nTile * TILE_N * KDIM;

    if (tid < TILE_N) biass[tid] = bias[nTile * TILE_N + tid];

    const int laneRowA = (lane & 7) + ((lane >> 3) & 1) * 8;
    const int laneColA = (lane >> 4) * 4;
    const int laneRowB = (lane & 7) + (lane >> 4) * 8;
    const int laneColB = ((lane >> 3) & 1) * 4;

    float acc[2][4][4];
    #pragma unroll
    for (int i = 0; i < 2; i++)
        #pragma unroll
        for (int j = 0; j < 4; j++)
            #pragma unroll
            for (int c = 0; c < 4; c++)
                acc[i][j][c] = 0.0f;

    auto load_chunk = [&](int kb) {
        int s = kb & 1;
        float* sA = stage0 + s * STG_FLOATS;
        float* sB = sA + SA_FLOATS;
        const float* ap = Ag + kb * KCHUNK;
        const float* bp = Bg + kb * KCHUNK;
        #pragma unroll
        for (int i = 0; i < 4; i++) {          // A: 1024 float4
            int idx = tid + i * 256;
            int r = idx >> 3;
            int c4 = (idx & 7) * 4;
            cp16s((uint32_t)__cvta_generic_to_shared(sA + r * LDSS + c4),
                  ap + (size_t)r * KDIM + c4);
        }
        #pragma unroll
        for (int i = 0; i < 2; i++) {          // B: 512 float4
            int idx = tid + i * 256;
            int r = idx >> 3;
            int c4 = (idx & 7) * 4;
            cp16s((uint32_t)__cvta_generic_to_shared(sB + r * LDSS + c4),
                  bp + (size_t)r * KDIM + c4);
        }
        asm volatile("cp.async.commit_group;");
    };

    load_chunk(0);

    for (int kb = 0; kb < KB; kb++) {
        asm volatile("cp.async.wait_group 0;");
        __syncthreads();

        if (kb + 1 < KB) load_chunk(kb + 1);   // overlaps compute(kb)

        int s = kb & 1;
        const float* sA = stage0 + s * STG_FLOATS;
        const float* sB = sA + SA_FLOATS;
        uint32_t sAu = (uint32_t)__cvta_generic_to_shared(sA);
        uint32_t sBu = (uint32_t)__cvta_generic_to_shared(sB);

        #pragma unroll
        for (int ks = 0; ks < 4; ks++) {
            uint32_t af[2][4];
            uint32_t bf[2][4];
            #pragma unroll
            for (int mt = 0; mt < 2; mt++) {
                uint32_t addr = sAu + 4 * ((wm + mt * 16 + laneRowA) * LDSS
                                           + ks * 8 + laneColA);
                ldsm4(af[mt][0], af[mt][1], af[mt][2], af[mt][3], addr);
            }
            #pragma unroll
            for (int p = 0; p < 2; p++) {
                uint32_t addr = sBu + 4 * ((wn + p * 16 + laneRowB) * LDSS
                                           + ks * 8 + laneColB);
                ldsm4(bf[p][0], bf[p][1], bf[p][2], bf[p][3], addr);
            }
            #pragma unroll
            for (int mt = 0; mt < 2; mt++) {
                #pragma unroll
                for (int nt = 0; nt < 4; nt++) {
                    uint32_t b0 = bf[nt >> 1][(nt & 1) * 2 + 0];
                    uint32_t b1 = bf[nt >> 1][(nt & 1) * 2 + 1];
                    asm volatile(
                        "mma.sync.aligned.m16n8k8.row.col.f32.tf32.tf32.f32 "
                        "{%0,%1,%2,%3}, {%4,%5,%6,%7}, {%8,%9}, {%0,%1,%2,%3};"
                        : "+f"(acc[mt][nt][0]), "+f"(acc[mt][nt][1]),
                          "+f"(acc[mt][nt][2]), "+f"(acc[mt][nt][3])
                        : "r"(af[mt][0]), "r"(af[mt][1]),
                          "r"(af[mt][2]), "r"(af[mt][3]),
                          "r"(b0), "r"(b1));
                }
            }
        }
    }

    // Epilogue: bias + NCHW scatter  out[nb][e][sp]
    #pragma unroll
    for (int mt = 0; mt < 2; mt++) {
        #pragma unroll
        for (int half = 0; half < 2; half++) {
            int m  = mTile * TILE_M + wm + mt * 16 + gId + half * 8;
            int nb = m / SPP;
            int sp = m - nb * SPP;
            float* ob = out + (size_t)nb * EMB * SPP + sp;
            #pragma unroll
            for (int nt = 0; nt < 4; nt++) {
                int eloc = wn + nt * 8 + tig * 2;
                int e0 = nTile * TILE_N + eloc;
                float v0 = acc[mt][nt][half * 2 + 0] + biass[eloc];
                float v1 = acc[mt][nt][half * 2 + 1] + biass[eloc + 1];
                ob[(size_t)e0 * SPP]       = v0;
                ob[(size_t)(e0 + 1) * SPP] = v1;
            }
        }
    }
}

// ---------------------------------------------------------------------------
// Launch
// ---------------------------------------------------------------------------
extern "C" void kernel_launch(void* const* d_in, const int* in_sizes, int n_in,
                              void* d_out, int out_size) {
    const float* x      = (const float*)d_in[0];
    const float* conv_w = (const float*)d_in[1];
    const float* conv_b = (const float*)d_in[2];
    const int*   idx0   = (const int*)d_in[3];
    const int*   idx1   = (const int*)d_in[4];
    const float* w      = (const float*)d_in[5];
    float* out = (float*)d_out;

    float* A = nullptr;
    cudaGetSymbolAddress((void**)&A, g_A);
    float* Wt = nullptr;
    cudaGetSymbolAddress((void**)&Wt, g_W);

    const int totalThreads = GATHER4 + WPREP4;
    fisheye_gather_kernel<<<(totalThreads + 255) / 256, 256>>>(
        x, idx0, idx1, w, conv_w, A, Wt);

    cudaFuncSetAttribute(fisheye_gemm_kernel,
                         cudaFuncAttributeMaxDynamicSharedMemorySize,
                         SMEM_TOTAL_BYTES);
    dim3 grid(EMB / TILE_N, MTOT / TILE_M);   // (12, 276)
    fisheye_gemm_kernel<<<grid, 256, SMEM_TOTAL_BYTES>>>(A, Wt, conv_b, out);
}

// round 10
// speedup vs baseline: 1.6701x; 1.6701x over previous
#include <cuda_runtime.h>
#include <cuda_fp16.h>
#include <cstdint>

// ---------------------------------------------------------------------------
// FishEyePatchEmbedding on GB300 (sm_103a) — fp16 mma.sync path
// fp16 has the SAME 10-bit mantissa as tf32 (identical rounding error) but
// m16n8k16 does 2x K per instruction and halves all smem/gmem traffic.
//   1) gather+lerp (fp32 math) -> A [35328, 768] fp16 (+ fused weight prep)
//   2) GEMM 128x128 tiles, 2 CTAs/SM, ldmatrix + mma.sync.m16n8k16.f16.f32
// ---------------------------------------------------------------------------

#define PLANE   (736 * 736)
#define NBATCH  32
#define EMB     768
#define KDIM    768
#define OHN     23
#define OWN     48
#define SPP     (OHN * OWN)       // 1104
#define MTOT    (NBATCH * SPP)    // 35328

#define TILE_M  128
#define TILE_N  128
#define KCHUNK  64                // halfs per K chunk (128 B/row)
#define KB      (KDIM / KCHUNK)   // 12
#define STAGES  3
#define LDSH    72                // padded smem stride (halfs) = 144 B

#define SA_HALFS   (TILE_M * LDSH)            // 9216
#define SB_HALFS   (TILE_N * LDSH)            // 9216
#define STG_HALFS  (SA_HALFS + SB_HALFS)      // 18432
#define SMEM_BIAS_BYTES 512                   // 128 f32
#define SMEM_TOTAL_BYTES (SMEM_BIAS_BYTES + STAGES * STG_HALFS * 2)  // 111104

__device__ __half g_A[(size_t)MTOT * KDIM];   // 54.3 MB scratch
__device__ __half g_W[(size_t)EMB * KDIM];    // 1.13 MB fp16 weights

#define GATHER4  (MTOT * (KDIM / 4))          // 6782976
#define WPREP4   (EMB * KDIM / 4)             // 147456

// ---------------------------------------------------------------------------
// Gather kernel: 4 k-elems/thread (R5-proven mapping), fp16 output,
// fused weight-prep tail.
// ---------------------------------------------------------------------------
__global__ void fisheye_gather_kernel(const float* __restrict__ x,
                                      const int*   __restrict__ idx0,
                                      const int*   __restrict__ idx1,
                                      const float* __restrict__ w,
                                      const float* __restrict__ conv_w,
                                      __half*      __restrict__ A,
                                      __half*      __restrict__ Wt) {
    int e4 = blockIdx.x * blockDim.x + threadIdx.x;
    if (e4 >= GATHER4) {
        int i = e4 - GATHER4;
        if (i < WPREP4) {
            float4 v = reinterpret_cast<const float4*>(conv_w)[i];
            __half2 h0 = __floats2half2_rn(v.x, v.y);
            __half2 h1 = __floats2half2_rn(v.z, v.w);
            uint2 st;
            st.x = *reinterpret_cast<uint32_t*>(&h0);
            st.y = *reinterpret_cast<uint32_t*>(&h1);
            *reinterpret_cast<uint2*>(Wt + i * 4) = st;
        }
        return;
    }

    int base = e4 * 4;
    int m = base / KDIM;
    int k = base - m * KDIM;

    int n  = m / SPP;
    int s  = m - n * SPP;
    int oh = s / OWN;
    int ow = s - oh * OWN;

    int c  = k >> 8;
    int r  = k & 255;
    int ky = r >> 4;
    int kx = r & 15;

    int t = (oh * 16 + ky) * 768 + ow * 16 + kx;

    const float* xp = x + (size_t)(n * 3 + c) * PLANE;

    int4   g0 = *reinterpret_cast<const int4*>(idx0 + t);
    int4   g1 = *reinterpret_cast<const int4*>(idx1 + t);
    float4 wt = *reinterpret_cast<const float4*>(w + t);

    float a0 = xp[g0.x], a1 = xp[g0.y], a2 = xp[g0.z], a3 = xp[g0.w];
    float b0 = xp[g1.x], b1 = xp[g1.y], b2 = xp[g1.z], b3 = xp[g1.w];

    float o0 = fmaf(b0 - a0, wt.x, a0);
    float o1 = fmaf(b1 - a1, wt.y, a1);
    float o2 = fmaf(b2 - a2, wt.z, a2);
    float o3 = fmaf(b3 - a3, wt.w, a3);

    __half2 h0 = __floats2half2_rn(o0, o1);
    __half2 h1 = __floats2half2_rn(o2, o3);
    uint2 st;
    st.x = *reinterpret_cast<uint32_t*>(&h0);
    st.y = *reinterpret_cast<uint32_t*>(&h1);
    *reinterpret_cast<uint2*>(A + base) = st;
}

// ---------------------------------------------------------------------------
__device__ __forceinline__ void cp16s(uint32_t sdst, const void* gsrc) {
    asm volatile("cp.async.cg.shared.global [%0], [%1], 16;" :: "r"(sdst), "l"(gsrc));
}
__device__ __forceinline__ void ldsm4(uint32_t& r0, uint32_t& r1,
                                      uint32_t& r2, uint32_t& r3, uint32_t a) {
    asm volatile("ldmatrix.sync.aligned.m8n8.x4.shared.b16 {%0,%1,%2,%3}, [%4];"
                 : "=r"(r0), "=r"(r1), "=r"(r2), "=r"(r3) : "r"(a));
}

// ---------------------------------------------------------------------------
// GEMM: grid (6, 276), 256 threads (8 warps 2x4), warp tile 64x32,
// 3-stage cp.async, fp16 m16n8k16, 2 CTAs/SM.
// ---------------------------------------------------------------------------
__global__ void __launch_bounds__(256, 2)
fisheye_gemm_kernel(const __half* __restrict__ A,
                    const __half* __restrict__ Wm,
                    const float*  __restrict__ bias,
                    float*        __restrict__ out) {
    extern __shared__ char smem[];
    float*  biass  = reinterpret_cast<float*>(smem);
    __half* stage0 = reinterpret_cast<__half*>(smem + SMEM_BIAS_BYTES);

    const int tid  = threadIdx.x;
    const int lane = tid & 31;
    const int warp = tid >> 5;
    const int wm   = (warp >> 2) * 64;   // 0 or 64
    const int wn   = (warp & 3) * 32;    // 0..96
    const int gId  = lane >> 2;
    const int tig  = lane & 3;

    const int nTile = blockIdx.x;
    const int mTile = blockIdx.y;

    const __half* Ag = A  + (size_t)mTile * TILE_M * KDIM;
    const __half* Bg = Wm + (size_t)nTile * TILE_N * KDIM;

    if (tid < TILE_N) biass[tid] = bias[nTile * TILE_N + tid];

    // fp16 ldmatrix lane address components (units: halfs)
    const int laneRowA = (lane & 7) + ((lane >> 3) & 1) * 8;
    const int laneColA = (lane >> 4) * 8;
    const int laneRowB = (lane & 7) + (lane >> 4) * 8;
    const int laneColB = ((lane >> 3) & 1) * 8;

    float acc[4][4][4];
    #pragma unroll
    for (int i = 0; i < 4; i++)
        #pragma unroll
        for (int j = 0; j < 4; j++)
            #pragma unroll
            for (int c = 0; c < 4; c++)
                acc[i][j][c] = 0.0f;

    // chunk loader: A/B each 128 rows x 128 B = 1024 x 16B, 256 threads
    auto load_chunk = [&](int kb) {
        int s = kb % STAGES;
        __half* sA = stage0 + s * STG_HALFS;
        __half* sB = sA + SA_HALFS;
        const __half* ap = Ag + kb * KCHUNK;
        const __half* bp = Bg + kb * KCHUNK;
        #pragma unroll
        for (int i = 0; i < 4; i++) {
            int idx = tid + i * 256;
            int r = idx >> 3;
            int c8 = (idx & 7) * 8;        // halfs within row
            cp16s((uint32_t)__cvta_generic_to_shared(sA + r * LDSH + c8),
                  ap + (size_t)r * KDIM + c8);
        }
        #pragma unroll
        for (int i = 0; i < 4; i++) {
            int idx = tid + i * 256;
            int r = idx >> 3;
            int c8 = (idx & 7) * 8;
            cp16s((uint32_t)__cvta_generic_to_shared(sB + r * LDSH + c8),
                  bp + (size_t)r * KDIM + c8);
        }
        asm volatile("cp.async.commit_group;");
    };

    load_chunk(0);
    load_chunk(1);

    for (int kb = 0; kb < KB; kb++) {
        if (kb < KB - 1) {
            asm volatile("cp.async.wait_group 1;");
        } else {
            asm volatile("cp.async.wait_group 0;");
        }
        __syncthreads();

        if (kb + 2 < KB) load_chunk(kb + 2);

        int s = kb % STAGES;
        const __half* sA = stage0 + s * STG_HALFS;
        const __half* sB = sA + SA_HALFS;
        uint32_t sAu = (uint32_t)__cvta_generic_to_shared(sA);
        uint32_t sBu = (uint32_t)__cvta_generic_to_shared(sB);

        #pragma unroll
        for (int ks = 0; ks < 4; ks++) {     // 4 x k16 per 64-half chunk
            uint32_t af[4][4];
            uint32_t bf[2][4];
            #pragma unroll
            for (int mt = 0; mt < 4; mt++) {
                uint32_t addr = sAu + 2 * ((wm + mt * 16 + laneRowA) * LDSH
                                           + ks * 16 + laneColA);
                ldsm4(af[mt][0], af[mt][1], af[mt][2], af[mt][3], addr);
            }
            #pragma unroll
            for (int p = 0; p < 2; p++) {    // each covers 2 n8-tiles
                uint32_t addr = sBu + 2 * ((wn + p * 16 + laneRowB) * LDSH
                                           + ks * 16 + laneColB);
                ldsm4(bf[p][0], bf[p][1], bf[p][2], bf[p][3], addr);
            }
            #pragma unroll
            for (int mt = 0; mt < 4; mt++) {
                #pragma unroll
                for (int nt = 0; nt < 4; nt++) {
                    uint32_t b0 = bf[nt >> 1][(nt & 1) * 2 + 0];
                    uint32_t b1 = bf[nt >> 1][(nt & 1) * 2 + 1];
                    asm volatile(
                        "mma.sync.aligned.m16n8k16.row.col.f32.f16.f16.f32 "
                        "{%0,%1,%2,%3}, {%4,%5,%6,%7}, {%8,%9}, {%0,%1,%2,%3};"
                        : "+f"(acc[mt][nt][0]), "+f"(acc[mt][nt][1]),
                          "+f"(acc[mt][nt][2]), "+f"(acc[mt][nt][3])
                        : "r"(af[mt][0]), "r"(af[mt][1]),
                          "r"(af[mt][2]), "r"(af[mt][3]),
                          "r"(b0), "r"(b1));
                }
            }
        }
    }

    // Epilogue: bias + NCHW scatter  out[nb][e][sp]
    #pragma unroll
    for (int mt = 0; mt < 4; mt++) {
        #pragma unroll
        for (int half = 0; half < 2; half++) {
            int m  = mTile * TILE_M + wm + mt * 16 + gId + half * 8;
            int nb = m / SPP;
            int sp = m - nb * SPP;
            float* ob = out + (size_t)nb * EMB * SPP + sp;
            #pragma unroll
            for (int nt = 0; nt < 4; nt++) {
                int eloc = wn + nt * 8 + tig * 2;
                int e0 = nTile * TILE_N + eloc;
                float v0 = acc[mt][nt][half * 2 + 0] + biass[eloc];
                float v1 = acc[mt][nt][half * 2 + 1] + biass[eloc + 1];
                ob[(size_t)e0 * SPP]       = v0;
                ob[(size_t)(e0 + 1) * SPP] = v1;
            }
        }
    }
}

// ---------------------------------------------------------------------------
// Launch
// ---------------------------------------------------------------------------
extern "C" void kernel_launch(void* const* d_in, const int* in_sizes, int n_in,
                              void* d_out, int out_size) {
    const float* x      = (const float*)d_in[0];
    const float* conv_w = (const float*)d_in[1];
    const float* conv_b = (const float*)d_in[2];
    const int*   idx0   = (const int*)d_in[3];
    const int*   idx1   = (const int*)d_in[4];
    const float* w      = (const float*)d_in[5];
    float* out = (float*)d_out;

    __half* A = nullptr;
    cudaGetSymbolAddress((void**)&A, g_A);
    __half* Wt = nullptr;
    cudaGetSymbolAddress((void**)&Wt, g_W);

    const int totalThreads = GATHER4 + WPREP4;
    fisheye_gather_kernel<<<(totalThreads + 255) / 256, 256>>>(
        x, idx0, idx1, w, conv_w, A, Wt);

    cudaFuncSetAttribute(fisheye_gemm_kernel,
                         cudaFuncAttributeMaxDynamicSharedMemorySize,
                         SMEM_TOTAL_BYTES);
    dim3 grid(EMB / TILE_N, MTOT / TILE_M);   // (6, 276)
    fisheye_gemm_kernel<<<grid, 256, SMEM_TOTAL_BYTES>>>(A, Wt, conv_b, out);
}